// round 1
// baseline (speedup 1.0000x reference)
#include <cuda_runtime.h>

#define NHEADS 16
#define DHEAD  64
#define SEQ    2048
#define BATCH  4
#define HD     1024

// scratch: q,k,v in [B, NH, S, D] layout (32 MB each)
__device__ float g_q[BATCH * NHEADS * SEQ * DHEAD];
__device__ float g_k[BATCH * NHEADS * SEQ * DHEAD];
__device__ float g_v[BATCH * NHEADS * SEQ * DHEAD];

// ---------------------------------------------------------------------------
// QKV projection: OUT[t, o] = sum_h HS[t,h] * W[o,h] + b[o], then (for q,k)
// interleaved rotary, stored to [B, NH, S, D] scratch.
// Tiling: 64x64 output tile per block, BK=16, 256 threads, 4x4 micro-tile.
// smem tiles stored [kk][m] with row pitch 68 floats (float4-aligned, low conflict).
// ---------------------------------------------------------------------------
__global__ void __launch_bounds__(256) qkv_gemm_kernel(
    const float* __restrict__ hs, const float* __restrict__ W,
    const float* __restrict__ bias, const float* __restrict__ rel, int which)
{
    __shared__ float As[16 * 68];
    __shared__ float Bs[16 * 68];

    float* out = (which == 0) ? g_q : (which == 1) ? g_k : g_v;

    const int tid = threadIdx.x;
    const int tx = tid & 15;        // output-col group
    const int ty = tid >> 4;        // output-row group
    const int bn = blockIdx.x * 64; // output col base
    const int bm = blockIdx.y * 64; // token row base

    const int lm = tid >> 2;          // 0..63 (row loaded by this thread)
    const int lk = (tid & 3) << 2;    // 0,4,8,12 (k offset, float4)

    const float* hp = hs + (size_t)(bm + lm) * HD + lk;
    const float* wp = W  + (size_t)(bn + lm) * HD + lk;

    float acc[4][4];
#pragma unroll
    for (int a = 0; a < 4; a++)
#pragma unroll
        for (int c = 0; c < 4; c++) acc[a][c] = 0.0f;

    for (int kt = 0; kt < HD; kt += 16) {
        float4 av = *(const float4*)(hp + kt);
        float4 bv = *(const float4*)(wp + kt);
        __syncthreads();
        As[(lk + 0) * 68 + lm] = av.x;
        As[(lk + 1) * 68 + lm] = av.y;
        As[(lk + 2) * 68 + lm] = av.z;
        As[(lk + 3) * 68 + lm] = av.w;
        Bs[(lk + 0) * 68 + lm] = bv.x;
        Bs[(lk + 1) * 68 + lm] = bv.y;
        Bs[(lk + 2) * 68 + lm] = bv.z;
        Bs[(lk + 3) * 68 + lm] = bv.w;
        __syncthreads();
#pragma unroll
        for (int kk = 0; kk < 16; kk++) {
            float4 a4 = *(const float4*)&As[kk * 68 + ty * 4];
            float4 b4 = *(const float4*)&Bs[kk * 68 + tx * 4];
            acc[0][0] += a4.x * b4.x; acc[0][1] += a4.x * b4.y;
            acc[0][2] += a4.x * b4.z; acc[0][3] += a4.x * b4.w;
            acc[1][0] += a4.y * b4.x; acc[1][1] += a4.y * b4.y;
            acc[1][2] += a4.y * b4.z; acc[1][3] += a4.y * b4.w;
            acc[2][0] += a4.z * b4.x; acc[2][1] += a4.z * b4.y;
            acc[2][2] += a4.z * b4.z; acc[2][3] += a4.z * b4.w;
            acc[3][0] += a4.w * b4.x; acc[3][1] += a4.w * b4.y;
            acc[3][2] += a4.w * b4.z; acc[3][3] += a4.w * b4.w;
        }
    }

    // epilogue: bias + interleaved rotary (for q,k) + scatter to [B,NH,S,D]
#pragma unroll
    for (int a = 0; a < 4; a++) {
        const int t = bm + ty * 4 + a;     // token
        const int b = t >> 11;             // batch
        const int s = t & 2047;            // seq pos
        const float* rs = rel + s * DHEAD;
#pragma unroll
        for (int p = 0; p < 2; p++) {
            const int o0 = bn + tx * 4 + p * 2;   // even output col
            const int h  = o0 >> 6;
            const int d0 = o0 & 63;               // even
            float x0 = acc[a][p * 2 + 0] + bias[o0];
            float x1 = acc[a][p * 2 + 1] + bias[o0 + 1];
            float y0, y1;
            if (which < 2) {
                // cos_pos[d] = rel[(d&~1)+1], sin_pos[d] = rel[d&~1]
                float cp = rs[d0 + 1];
                float sp = rs[d0];
                y0 = x0 * cp - x1 * sp;
                y1 = x1 * cp + x0 * sp;
            } else {
                y0 = x0; y1 = x1;
            }
            const int idx = (((b * NHEADS + h) * SEQ) + s) * DHEAD + d0;
            out[idx]     = y0;
            out[idx + 1] = y1;
        }
    }
}

// ---------------------------------------------------------------------------
// Flash attention: one block = 64 queries of one (b,h). 256 threads.
// K-loop over 32 tiles of 64 keys. Online softmax, warp-level row state
// (warp w owns rows w*8 .. w*8+7). P written to smem for the PV phase.
// smem pitch 68 floats everywhere (float4-aligned, conflict-friendly).
// ---------------------------------------------------------------------------
#define ATTN_SMEM_FLOATS (4 * 64 * 68 + 128)

__global__ void __launch_bounds__(256) attn_kernel(
    const float* __restrict__ mask, float* __restrict__ out)
{
    extern __shared__ float sm[];
    float* Qs   = sm;                 // 64*68
    float* Ks   = Qs + 64 * 68;
    float* Vs   = Ks + 64 * 68;
    float* Ps   = Vs + 64 * 68;
    float* corr = Ps + 64 * 68;       // 64
    float* lrow = corr + 64;          // 64

    const int tid  = threadIdx.x;
    const int lane = tid & 31;
    const int w    = tid >> 5;        // warp 0..7
    const int qt = blockIdx.x;        // q tile
    const int h  = blockIdx.y;
    const int b  = blockIdx.z;
    const int bh = b * NHEADS + h;

    const float* qb = g_q + ((size_t)bh * SEQ + qt * 64) * DHEAD;
    const float* kb = g_k + (size_t)bh * SEQ * DHEAD;
    const float* vb = g_v + (size_t)bh * SEQ * DHEAD;
    const float* mb = mask + b * SEQ;

    for (int idx = tid; idx < 4096; idx += 256)
        Qs[(idx >> 6) * 68 + (idx & 63)] = qb[idx];

    float mrow[8], lreg[8];
#pragma unroll
    for (int r = 0; r < 8; r++) { mrow[r] = -1e30f; lreg[r] = 0.0f; }

    const int ti = tid >> 4;          // 0..15  (row group for PV)
    const int tj = tid & 15;          // 0..15  (dim group for PV)
    float acc[4][4];
#pragma unroll
    for (int a = 0; a < 4; a++)
#pragma unroll
        for (int c = 0; c < 4; c++) acc[a][c] = 0.0f;

    for (int kt = 0; kt < 32; kt++) {
        __syncthreads();  // previous PV phase done reading Ks/Vs/Ps
        const float* kg = kb + kt * 4096;
        const float* vg = vb + kt * 4096;
        for (int idx = tid; idx < 4096; idx += 256) {
            const int r = idx >> 6, c = idx & 63;
            Ks[r * 68 + c] = kg[idx];
            Vs[r * 68 + c] = vg[idx];
        }
        __syncthreads();

        const float mk0 = mb[kt * 64 + lane];
        const float mk1 = mb[kt * 64 + lane + 32];

#pragma unroll
        for (int r = 0; r < 8; r++) {
            const int i = w * 8 + r;
            float s0 = 0.0f, s1 = 0.0f;
#pragma unroll
            for (int k4 = 0; k4 < 16; k4++) {
                float4 q4 = *(const float4*)&Qs[i * 68 + k4 * 4];
                float4 ka = *(const float4*)&Ks[lane * 68 + k4 * 4];
                float4 kc = *(const float4*)&Ks[(lane + 32) * 68 + k4 * 4];
                s0 += q4.x * ka.x + q4.y * ka.y + q4.z * ka.z + q4.w * ka.w;
                s1 += q4.x * kc.x + q4.y * kc.y + q4.z * kc.z + q4.w * kc.w;
            }
            s0 = s0 * 0.125f + mk0;   // 1/sqrt(64)
            s1 = s1 * 0.125f + mk1;

            float tm = fmaxf(s0, s1);
#pragma unroll
            for (int off = 16; off > 0; off >>= 1)
                tm = fmaxf(tm, __shfl_xor_sync(0xffffffffu, tm, off));
            const float nm = fmaxf(mrow[r], tm);
            const float cr = __expf(mrow[r] - nm);
            mrow[r] = nm;
            const float p0 = __expf(s0 - nm);
            const float p1 = __expf(s1 - nm);
            float rsum = p0 + p1;
#pragma unroll
            for (int off = 16; off > 0; off >>= 1)
                rsum += __shfl_xor_sync(0xffffffffu, rsum, off);
            lreg[r] = lreg[r] * cr + rsum;
            Ps[i * 68 + lane]      = p0;
            Ps[i * 68 + lane + 32] = p1;
            if (lane == 0) corr[i] = cr;
        }
        __syncthreads();

        // PV phase: thread handles rows ti*4..ti*4+3, dims tj*4..tj*4+3
#pragma unroll
        for (int a = 0; a < 4; a++) {
            const float cr = corr[ti * 4 + a];
            acc[a][0] *= cr; acc[a][1] *= cr; acc[a][2] *= cr; acc[a][3] *= cr;
        }
        for (int j = 0; j < 64; j++) {
            float4 v4 = *(const float4*)&Vs[j * 68 + tj * 4];
#pragma unroll
            for (int a = 0; a < 4; a++) {
                const float p = Ps[(ti * 4 + a) * 68 + j];
                acc[a][0] += p * v4.x;
                acc[a][1] += p * v4.y;
                acc[a][2] += p * v4.z;
                acc[a][3] += p * v4.w;
            }
        }
    }

    if (lane == 0) {
#pragma unroll
        for (int r = 0; r < 8; r++) lrow[w * 8 + r] = lreg[r];
    }
    __syncthreads();

    // out[b][s][h*64 + d]
#pragma unroll
    for (int a = 0; a < 4; a++) {
        const int i = ti * 4 + a;
        const float inv = 1.0f / lrow[i];
        const int s = qt * 64 + i;
        float4 o4;
        o4.x = acc[a][0] * inv;
        o4.y = acc[a][1] * inv;
        o4.z = acc[a][2] * inv;
        o4.w = acc[a][3] * inv;
        float* op = out + (((size_t)b * SEQ + s) * NHEADS + h) * DHEAD + tj * 4;
        *(float4*)op = o4;
    }
}

extern "C" void kernel_launch(void* const* d_in, const int* in_sizes, int n_in,
                              void* d_out, int out_size)
{
    const float* hs   = (const float*)d_in[0];  // [4,2048,1024]
    const float* mask = (const float*)d_in[1];  // [4,1,1,2048]
    const float* rel  = (const float*)d_in[2];  // [1,1,2048,64]
    const float* Wq   = (const float*)d_in[3];
    const float* bq   = (const float*)d_in[4];
    const float* Wk   = (const float*)d_in[5];
    const float* bk   = (const float*)d_in[6];
    const float* Wv   = (const float*)d_in[7];
    const float* bv   = (const float*)d_in[8];
    float* out = (float*)d_out;

    (void)in_sizes; (void)n_in; (void)out_size;

    cudaFuncSetAttribute(attn_kernel, cudaFuncAttributeMaxDynamicSharedMemorySize,
                         ATTN_SMEM_FLOATS * (int)sizeof(float));

    dim3 ggrid(HD / 64, (BATCH * SEQ) / 64);
    qkv_gemm_kernel<<<ggrid, 256>>>(hs, Wq, bq, rel, 0);
    qkv_gemm_kernel<<<ggrid, 256>>>(hs, Wk, bk, rel, 1);
    qkv_gemm_kernel<<<ggrid, 256>>>(hs, Wv, bv, rel, 2);

    dim3 agrid(SEQ / 64, NHEADS, BATCH);
    attn_kernel<<<agrid, 256, ATTN_SMEM_FLOATS * (int)sizeof(float)>>>(mask, out);
}

// round 3
// speedup vs baseline: 4.3253x; 4.3253x over previous
#include <cuda_runtime.h>
#include <cstdint>

#define NHEADS 16
#define DHEAD  64
#define SEQ    2048
#define BATCH  4
#define HD     1024

// scratch: q,k,v in [B, NH, S, D] layout (32 MB each)
__device__ float g_q[BATCH * NHEADS * SEQ * DHEAD];
__device__ float g_k[BATCH * NHEADS * SEQ * DHEAD];
__device__ float g_v[BATCH * NHEADS * SEQ * DHEAD];

__device__ __forceinline__ uint32_t f2tf(float x) {
    uint32_t r;
    asm("cvt.rna.tf32.f32 %0, %1;" : "=r"(r) : "f"(x));
    return r;
}
__device__ __forceinline__ float f2tf_f(float x) {
    return __uint_as_float(f2tf(x));
}

// D += A(16x8) * B(8x8), tf32 inputs, fp32 accum
__device__ __forceinline__ void mma8(float* d, const uint32_t* a, const uint32_t* b) {
    asm volatile(
        "mma.sync.aligned.m16n8k8.row.col.f32.tf32.tf32.f32 "
        "{%0,%1,%2,%3},{%4,%5,%6,%7},{%8,%9},{%0,%1,%2,%3};"
        : "+f"(d[0]), "+f"(d[1]), "+f"(d[2]), "+f"(d[3])
        : "r"(a[0]), "r"(a[1]), "r"(a[2]), "r"(a[3]), "r"(b[0]), "r"(b[1]));
}

// ---------------------------------------------------------------------------
// QKV projection (tf32 tensor-core): OUT[t,o] = HS[t,:]·W[o,:] + b[o],
// then interleaved rotary for q,k; scatter to [B,NH,S,D].
// Block tile 128x64, BK=32. 8 warps (4x2), warp tile 32x32 = 2x4 m16n8k8.
// Smem row-major, pitch+4: all fragment LDS conflict-free.
// blockIdx.z selects q/k/v.
// ---------------------------------------------------------------------------
__global__ void __launch_bounds__(256) qkv_mma_kernel(
    const float* __restrict__ hs,
    const float* __restrict__ Wq, const float* __restrict__ bq,
    const float* __restrict__ Wk, const float* __restrict__ bk,
    const float* __restrict__ Wv, const float* __restrict__ bv,
    const float* __restrict__ rel)
{
    __shared__ float As[128 * 36];
    __shared__ float Bs[64 * 36];

    const int which = blockIdx.z;
    const float* W    = (which == 0) ? Wq : (which == 1) ? Wk : Wv;
    const float* bias = (which == 0) ? bq : (which == 1) ? bk : bv;
    float* out        = (which == 0) ? g_q : (which == 1) ? g_k : g_v;

    const int tid  = threadIdx.x;
    const int lane = tid & 31;
    const int warp = tid >> 5;
    const int gq   = lane >> 2;   // group id (row within frag)
    const int gr   = lane & 3;    // thread-in-group (k within frag)
    const int wm   = (warp >> 1) * 32;
    const int wn   = (warp & 1) * 32;
    const int bm   = blockIdx.y * 128;
    const int bn   = blockIdx.x * 64;

    float acc[2][4][4];
#pragma unroll
    for (int mt = 0; mt < 2; mt++)
#pragma unroll
        for (int nt = 0; nt < 4; nt++)
#pragma unroll
            for (int c = 0; c < 4; c++) acc[mt][nt][c] = 0.0f;

    for (int kt = 0; kt < HD; kt += 32) {
        __syncthreads();
        // A: 128x32 floats = 1024 float4, 4 per thread, cvt to tf32 at store
#pragma unroll
        for (int i = 0; i < 4; i++) {
            int id = tid + i * 256;
            int r = id >> 3, kc = (id & 7) * 4;
            float4 v = *(const float4*)(hs + (size_t)(bm + r) * HD + kt + kc);
            *(float4*)&As[r * 36 + kc] =
                make_float4(f2tf_f(v.x), f2tf_f(v.y), f2tf_f(v.z), f2tf_f(v.w));
        }
        // B: 64x32 = 512 float4, 2 per thread
#pragma unroll
        for (int i = 0; i < 2; i++) {
            int id = tid + i * 256;
            int r = id >> 3, kc = (id & 7) * 4;
            float4 v = *(const float4*)(W + (size_t)(bn + r) * HD + kt + kc);
            *(float4*)&Bs[r * 36 + kc] =
                make_float4(f2tf_f(v.x), f2tf_f(v.y), f2tf_f(v.z), f2tf_f(v.w));
        }
        __syncthreads();

#pragma unroll
        for (int k8 = 0; k8 < 32; k8 += 8) {
            uint32_t af[2][4];
#pragma unroll
            for (int mt = 0; mt < 2; mt++) {
                const int r0 = wm + mt * 16 + gq;
                af[mt][0] = __float_as_uint(As[r0 * 36 + k8 + gr]);
                af[mt][1] = __float_as_uint(As[(r0 + 8) * 36 + k8 + gr]);
                af[mt][2] = __float_as_uint(As[r0 * 36 + k8 + 4 + gr]);
                af[mt][3] = __float_as_uint(As[(r0 + 8) * 36 + k8 + 4 + gr]);
            }
#pragma unroll
            for (int nt = 0; nt < 4; nt++) {
                const int c0 = wn + nt * 8 + gq;
                uint32_t bf[2];
                bf[0] = __float_as_uint(Bs[c0 * 36 + k8 + gr]);
                bf[1] = __float_as_uint(Bs[c0 * 36 + k8 + 4 + gr]);
                mma8(acc[0][nt], af[0], bf);
                mma8(acc[1][nt], af[1], bf);
            }
        }
    }

    // epilogue: bias + rotary + scatter
#pragma unroll
    for (int mt = 0; mt < 2; mt++) {
#pragma unroll
        for (int rh = 0; rh < 2; rh++) {
            const int row = bm + wm + mt * 16 + gq + rh * 8;  // token
            const int b = row >> 11;
            const int s = row & 2047;
            const float* rs = rel + s * DHEAD;
#pragma unroll
            for (int nt = 0; nt < 4; nt++) {
                const int o0 = bn + wn + nt * 8 + 2 * gr;   // even col
                float x0 = acc[mt][nt][rh * 2 + 0] + bias[o0];
                float x1 = acc[mt][nt][rh * 2 + 1] + bias[o0 + 1];
                const int d0 = o0 & 63;
                float y0 = x0, y1 = x1;
                if (which < 2) {
                    const float cp = rs[d0 + 1];
                    const float sp = rs[d0];
                    y0 = x0 * cp - x1 * sp;
                    y1 = x1 * cp + x0 * sp;
                }
                const int h = o0 >> 6;
                const size_t idx = (((size_t)(b * NHEADS + h) * SEQ) + s) * DHEAD + d0;
                *(float2*)&out[idx] = make_float2(y0, y1);
            }
        }
    }
}

// ---------------------------------------------------------------------------
// Flash attention, tf32 tensor-core. Block = 64 queries of one (b,h).
// 8 warps: warp (w>>1) row-band of 16, (w&1) col-half of 32.
// S = Q·K^T via mma, SIMT online softmax, O += P·V via mma.
// All smem tiles row-major pitch 68; operands pre-rounded to tf32.
// ---------------------------------------------------------------------------
#define ASMEM_FLOATS (4 * 64 * 68 + 2048 + 128)

__global__ void __launch_bounds__(256) attn_mma_kernel(
    const float* __restrict__ mask, float* __restrict__ out)
{
    extern __shared__ float sm[];
    float* Qs   = sm;               // [m][d]   64x68
    float* Ks   = Qs + 64 * 68;     // [key][d] 64x68
    float* Vs   = Ks + 64 * 68;     // [key][d] 64x68
    float* Ps   = Vs + 64 * 68;     // [m][key] 64x68
    float* msk  = Ps + 64 * 68;     // 2048
    float* corr = msk + 2048;       // 64
    float* lrow = corr + 64;        // 64

    const int tid  = threadIdx.x;
    const int lane = tid & 31;
    const int warp = tid >> 5;
    const int gq = lane >> 2;
    const int gr = lane & 3;
    const int wm = (warp >> 1) * 16;
    const int wn = (warp & 1) * 32;
    const int qt = blockIdx.x;
    const int h  = blockIdx.y;
    const int b  = blockIdx.z;
    const int bh = b * NHEADS + h;

    const float* qb = g_q + ((size_t)bh * SEQ + qt * 64) * DHEAD;
    const float* kb = g_k + (size_t)bh * SEQ * DHEAD;
    const float* vb = g_v + (size_t)bh * SEQ * DHEAD;
    const float* mb = mask + b * SEQ;

    for (int i = tid; i < SEQ; i += 256) msk[i] = mb[i];
#pragma unroll
    for (int i = 0; i < 4; i++) {
        int id = tid + i * 256;
        int m = id >> 4, dc = (id & 15) * 4;
        float4 v = *(const float4*)(qb + m * 64 + dc);
        *(float4*)&Qs[m * 68 + dc] =
            make_float4(f2tf_f(v.x), f2tf_f(v.y), f2tf_f(v.z), f2tf_f(v.w));
    }

    float rmax[8], rsum[8];
#pragma unroll
    for (int r = 0; r < 8; r++) { rmax[r] = -1e30f; rsum[r] = 0.0f; }

    float oacc[4][4];
#pragma unroll
    for (int nt = 0; nt < 4; nt++)
#pragma unroll
        for (int c = 0; c < 4; c++) oacc[nt][c] = 0.0f;

    for (int kt = 0; kt < 32; kt++) {
        __syncthreads();   // prior PV done with Ks/Vs/Ps
        const float* kg = kb + kt * 4096;
        const float* vg = vb + kt * 4096;
#pragma unroll
        for (int i = 0; i < 4; i++) {
            int id = tid + i * 256;
            int m = id >> 4, dc = (id & 15) * 4;
            float4 kv = *(const float4*)(kg + m * 64 + dc);
            float4 vv = *(const float4*)(vg + m * 64 + dc);
            *(float4*)&Ks[m * 68 + dc] =
                make_float4(f2tf_f(kv.x), f2tf_f(kv.y), f2tf_f(kv.z), f2tf_f(kv.w));
            *(float4*)&Vs[m * 68 + dc] =
                make_float4(f2tf_f(vv.x), f2tf_f(vv.y), f2tf_f(vv.z), f2tf_f(vv.w));
        }
        __syncthreads();

        // ---- S = Q K^T ----
        float sacc[4][4];
#pragma unroll
        for (int nt = 0; nt < 4; nt++)
#pragma unroll
            for (int c = 0; c < 4; c++) sacc[nt][c] = 0.0f;

        const int m0 = wm + gq;
#pragma unroll
        for (int k8 = 0; k8 < 64; k8 += 8) {
            uint32_t af[4];
            af[0] = __float_as_uint(Qs[m0 * 68 + k8 + gr]);
            af[1] = __float_as_uint(Qs[(m0 + 8) * 68 + k8 + gr]);
            af[2] = __float_as_uint(Qs[m0 * 68 + k8 + 4 + gr]);
            af[3] = __float_as_uint(Qs[(m0 + 8) * 68 + k8 + 4 + gr]);
#pragma unroll
            for (int nt = 0; nt < 4; nt++) {
                const int n0 = wn + nt * 8 + gq;   // key index
                uint32_t bf[2];
                bf[0] = __float_as_uint(Ks[n0 * 68 + k8 + gr]);
                bf[1] = __float_as_uint(Ks[n0 * 68 + k8 + 4 + gr]);
                mma8(sacc[nt], af, bf);
            }
        }
        // write scaled + masked scores
#pragma unroll
        for (int nt = 0; nt < 4; nt++) {
            const int c0 = wn + nt * 8 + 2 * gr;
            const float mk0 = msk[kt * 64 + c0];
            const float mk1 = msk[kt * 64 + c0 + 1];
            *(float2*)&Ps[m0 * 68 + c0] =
                make_float2(sacc[nt][0] * 0.125f + mk0, sacc[nt][1] * 0.125f + mk1);
            *(float2*)&Ps[(m0 + 8) * 68 + c0] =
                make_float2(sacc[nt][2] * 0.125f + mk0, sacc[nt][3] * 0.125f + mk1);
        }
        __syncthreads();

        // ---- online softmax: warp w owns rows w*8 .. w*8+7 ----
#pragma unroll
        for (int r = 0; r < 8; r++) {
            const int i = warp * 8 + r;
            float s0 = Ps[i * 68 + lane];
            float s1 = Ps[i * 68 + lane + 32];
            float tm = fmaxf(s0, s1);
#pragma unroll
            for (int off = 16; off > 0; off >>= 1)
                tm = fmaxf(tm, __shfl_xor_sync(0xffffffffu, tm, off));
            const float nm = fmaxf(rmax[r], tm);
            const float cr = __expf(rmax[r] - nm);
            rmax[r] = nm;
            const float p0 = __expf(s0 - nm);
            const float p1 = __expf(s1 - nm);
            float rs2 = p0 + p1;
#pragma unroll
            for (int off = 16; off > 0; off >>= 1)
                rs2 += __shfl_xor_sync(0xffffffffu, rs2, off);
            rsum[r] = rsum[r] * cr + rs2;
            Ps[i * 68 + lane]      = f2tf_f(p0);
            Ps[i * 68 + lane + 32] = f2tf_f(p1);
            if (lane == 0) corr[i] = cr;
        }
        __syncthreads();

        // ---- O = O*corr + P·V ----
        {
            const float c0 = corr[wm + gq];
            const float c1 = corr[wm + 8 + gq];
#pragma unroll
            for (int nt = 0; nt < 4; nt++) {
                oacc[nt][0] *= c0; oacc[nt][1] *= c0;
                oacc[nt][2] *= c1; oacc[nt][3] *= c1;
            }
        }
#pragma unroll
        for (int k8 = 0; k8 < 64; k8 += 8) {
            uint32_t af[4];
            af[0] = __float_as_uint(Ps[m0 * 68 + k8 + gr]);
            af[1] = __float_as_uint(Ps[(m0 + 8) * 68 + k8 + gr]);
            af[2] = __float_as_uint(Ps[m0 * 68 + k8 + 4 + gr]);
            af[3] = __float_as_uint(Ps[(m0 + 8) * 68 + k8 + 4 + gr]);
#pragma unroll
            for (int nt = 0; nt < 4; nt++) {
                const int d0 = wn + nt * 8 + gq;   // out dim
                uint32_t bf[2];
                bf[0] = __float_as_uint(Vs[(k8 + gr) * 68 + d0]);
                bf[1] = __float_as_uint(Vs[(k8 + 4 + gr) * 68 + d0]);
                mma8(oacc[nt], af, bf);
            }
        }
    }

    if (lane == 0) {
#pragma unroll
        for (int r = 0; r < 8; r++) lrow[warp * 8 + r] = rsum[r];
    }
    __syncthreads();

    {
        const int m0 = wm + gq;
        const float inv0 = 1.0f / lrow[m0];
        const float inv1 = 1.0f / lrow[m0 + 8];
        const int s0r = qt * 64 + m0;
        const int s1r = s0r + 8;
#pragma unroll
        for (int nt = 0; nt < 4; nt++) {
            const int d0c = wn + nt * 8 + 2 * gr;
            const int hcol = h * 64 + d0c;
            const size_t i0 = ((size_t)(b * SEQ + s0r)) * 1024 + hcol;
            const size_t i1 = ((size_t)(b * SEQ + s1r)) * 1024 + hcol;
            *(float2*)&out[i0] = make_float2(oacc[nt][0] * inv0, oacc[nt][1] * inv0);
            *(float2*)&out[i1] = make_float2(oacc[nt][2] * inv1, oacc[nt][3] * inv1);
        }
    }
}

extern "C" void kernel_launch(void* const* d_in, const int* in_sizes, int n_in,
                              void* d_out, int out_size)
{
    const float* hs   = (const float*)d_in[0];
    const float* mask = (const float*)d_in[1];
    const float* rel  = (const float*)d_in[2];
    const float* Wq   = (const float*)d_in[3];
    const float* bq   = (const float*)d_in[4];
    const float* Wk   = (const float*)d_in[5];
    const float* bk   = (const float*)d_in[6];
    const float* Wv   = (const float*)d_in[7];
    const float* bv   = (const float*)d_in[8];
    float* out = (float*)d_out;
    (void)in_sizes; (void)n_in; (void)out_size;

    cudaFuncSetAttribute(attn_mma_kernel, cudaFuncAttributeMaxDynamicSharedMemorySize,
                         ASMEM_FLOATS * (int)sizeof(float));

    dim3 ggrid(HD / 64, (BATCH * SEQ) / 128, 3);
    qkv_mma_kernel<<<ggrid, 256>>>(hs, Wq, bq, Wk, bk, Wv, bv, rel);

    dim3 agrid(SEQ / 64, NHEADS, BATCH);
    attn_mma_kernel<<<agrid, 256, ASMEM_FLOATS * (int)sizeof(float)>>>(mask, out);
}

// round 8
// speedup vs baseline: 6.9738x; 1.6123x over previous
#include <cuda_runtime.h>
#include <cstdint>

#define NHEADS 16
#define DHEAD  64
#define SEQ    2048
#define BATCH  4
#define HD     1024

// scratch: q,k,v in [B, NH, S, D] layout (32 MB each)
__device__ float g_q[BATCH * NHEADS * SEQ * DHEAD];
__device__ float g_k[BATCH * NHEADS * SEQ * DHEAD];
__device__ float g_v[BATCH * NHEADS * SEQ * DHEAD];

__device__ __forceinline__ uint32_t f2tf(float x) {
    uint32_t r;
    asm("cvt.rna.tf32.f32 %0, %1;" : "=r"(r) : "f"(x));
    return r;
}
__device__ __forceinline__ float f2tf_f(float x) {
    return __uint_as_float(f2tf(x));
}

// D += A(16x8) * B(8x8), tf32 inputs, fp32 accum
__device__ __forceinline__ void mma8(float* d, const uint32_t* a, const uint32_t* b) {
    asm volatile(
        "mma.sync.aligned.m16n8k8.row.col.f32.tf32.tf32.f32 "
        "{%0,%1,%2,%3},{%4,%5,%6,%7},{%8,%9},{%0,%1,%2,%3};"
        : "+f"(d[0]), "+f"(d[1]), "+f"(d[2]), "+f"(d[3])
        : "r"(a[0]), "r"(a[1]), "r"(a[2]), "r"(a[3]), "r"(b[0]), "r"(b[1]));
}

// ---------------------------------------------------------------------------
// QKV projection (tf32 tensor-core), unchanged from round 3 (proven).
// ---------------------------------------------------------------------------
__global__ void __launch_bounds__(256) qkv_mma_kernel(
    const float* __restrict__ hs,
    const float* __restrict__ Wq, const float* __restrict__ bq,
    const float* __restrict__ Wk, const float* __restrict__ bk,
    const float* __restrict__ Wv, const float* __restrict__ bv,
    const float* __restrict__ rel)
{
    __shared__ float As[128 * 36];
    __shared__ float Bs[64 * 36];

    const int which = blockIdx.z;
    const float* W    = (which == 0) ? Wq : (which == 1) ? Wk : Wv;
    const float* bias = (which == 0) ? bq : (which == 1) ? bk : bv;
    float* out        = (which == 0) ? g_q : (which == 1) ? g_k : g_v;

    const int tid  = threadIdx.x;
    const int lane = tid & 31;
    const int warp = tid >> 5;
    const int gq   = lane >> 2;
    const int gr   = lane & 3;
    const int wm   = (warp >> 1) * 32;
    const int wn   = (warp & 1) * 32;
    const int bm   = blockIdx.y * 128;
    const int bn   = blockIdx.x * 64;

    float acc[2][4][4];
#pragma unroll
    for (int mt = 0; mt < 2; mt++)
#pragma unroll
        for (int nt = 0; nt < 4; nt++)
#pragma unroll
            for (int c = 0; c < 4; c++) acc[mt][nt][c] = 0.0f;

    for (int kt = 0; kt < HD; kt += 32) {
        __syncthreads();
#pragma unroll
        for (int i = 0; i < 4; i++) {
            int id = tid + i * 256;
            int r = id >> 3, kc = (id & 7) * 4;
            float4 v = *(const float4*)(hs + (size_t)(bm + r) * HD + kt + kc);
            *(float4*)&As[r * 36 + kc] =
                make_float4(f2tf_f(v.x), f2tf_f(v.y), f2tf_f(v.z), f2tf_f(v.w));
        }
#pragma unroll
        for (int i = 0; i < 2; i++) {
            int id = tid + i * 256;
            int r = id >> 3, kc = (id & 7) * 4;
            float4 v = *(const float4*)(W + (size_t)(bn + r) * HD + kt + kc);
            *(float4*)&Bs[r * 36 + kc] =
                make_float4(f2tf_f(v.x), f2tf_f(v.y), f2tf_f(v.z), f2tf_f(v.w));
        }
        __syncthreads();

#pragma unroll
        for (int k8 = 0; k8 < 32; k8 += 8) {
            uint32_t af[2][4];
#pragma unroll
            for (int mt = 0; mt < 2; mt++) {
                const int r0 = wm + mt * 16 + gq;
                af[mt][0] = __float_as_uint(As[r0 * 36 + k8 + gr]);
                af[mt][1] = __float_as_uint(As[(r0 + 8) * 36 + k8 + gr]);
                af[mt][2] = __float_as_uint(As[r0 * 36 + k8 + 4 + gr]);
                af[mt][3] = __float_as_uint(As[(r0 + 8) * 36 + k8 + 4 + gr]);
            }
#pragma unroll
            for (int nt = 0; nt < 4; nt++) {
                const int c0 = wn + nt * 8 + gq;
                uint32_t bf[2];
                bf[0] = __float_as_uint(Bs[c0 * 36 + k8 + gr]);
                bf[1] = __float_as_uint(Bs[c0 * 36 + k8 + 4 + gr]);
                mma8(acc[0][nt], af[0], bf);
                mma8(acc[1][nt], af[1], bf);
            }
        }
    }

#pragma unroll
    for (int mt = 0; mt < 2; mt++) {
#pragma unroll
        for (int rh = 0; rh < 2; rh++) {
            const int row = bm + wm + mt * 16 + gq + rh * 8;
            const int b = row >> 11;
            const int s = row & 2047;
            const float* rs = rel + s * DHEAD;
#pragma unroll
            for (int nt = 0; nt < 4; nt++) {
                const int o0 = bn + wn + nt * 8 + 2 * gr;
                float x0 = acc[mt][nt][rh * 2 + 0] + bias[o0];
                float x1 = acc[mt][nt][rh * 2 + 1] + bias[o0 + 1];
                const int d0 = o0 & 63;
                float y0 = x0, y1 = x1;
                if (which < 2) {
                    const float cp = rs[d0 + 1];
                    const float sp = rs[d0];
                    y0 = x0 * cp - x1 * sp;
                    y1 = x1 * cp + x0 * sp;
                }
                const int h = o0 >> 6;
                const size_t idx = (((size_t)(b * NHEADS + h) * SEQ) + s) * DHEAD + d0;
                *(float2*)&out[idx] = make_float2(y0, y1);
            }
        }
    }
}

// ---------------------------------------------------------------------------
// Flash attention v2: 128-query tile, 128 threads (4 warps).
// Warp w owns rows w*32 .. w*32+31 (mt=2 x m16) and ALL 64 key-cols (nt=8).
// S stays in registers; softmax is warp-local (intra-quad shuffles only).
// Only P goes to smem (tf32) for the PV MMA A-fragments. 2 syncthreads/tile.
// ---------------------------------------------------------------------------
#define QT 128
#define ASMEM_FLOATS (QT * 68 + 64 * 68 + 64 * 68 + QT * 68 + 2048)

__global__ void __launch_bounds__(128, 2) attn_mma_kernel(
    const float* __restrict__ mask, float* __restrict__ out)
{
    extern __shared__ float sm[];
    float* Qs  = sm;                    // [m][d]   128x68 (tf32)
    float* Ks  = Qs + QT * 68;          // [key][d] 64x68  (tf32)
    float* Vs  = Ks + 64 * 68;          // [key][d] 64x68  (tf32)
    float* Ps  = Vs + 64 * 68;          // [m][key] 128x68 (tf32)
    float* msk = Ps + QT * 68;          // 2048

    const int tid  = threadIdx.x;
    const int lane = tid & 31;
    const int warp = tid >> 5;          // 0..3
    const int gq = lane >> 2;
    const int gr = lane & 3;
    const int wm = warp * 32;
    const int qt = blockIdx.x;
    const int h  = blockIdx.y;
    const int b  = blockIdx.z;
    const int bh = b * NHEADS + h;

    const float* qb = g_q + ((size_t)bh * SEQ + qt * QT) * DHEAD;
    const float* kb = g_k + (size_t)bh * SEQ * DHEAD;
    const float* vb = g_v + (size_t)bh * SEQ * DHEAD;
    const float* mb = mask + b * SEQ;

    for (int i = tid; i < SEQ; i += 128) msk[i] = mb[i];
#pragma unroll
    for (int i = 0; i < 16; i++) {
        int id = tid + i * 128;
        int m = id >> 4, dc = (id & 15) * 4;
        float4 v = *(const float4*)(qb + m * 64 + dc);
        *(float4*)&Qs[m * 68 + dc] =
            make_float4(f2tf_f(v.x), f2tf_f(v.y), f2tf_f(v.z), f2tf_f(v.w));
    }

    float rmax[2][2], rsum[2][2];
#pragma unroll
    for (int mt = 0; mt < 2; mt++) {
        rmax[mt][0] = -1e30f; rmax[mt][1] = -1e30f;
        rsum[mt][0] = 0.0f;   rsum[mt][1] = 0.0f;
    }

    float oacc[2][8][4];
#pragma unroll
    for (int mt = 0; mt < 2; mt++)
#pragma unroll
        for (int nt = 0; nt < 8; nt++)
#pragma unroll
            for (int c = 0; c < 4; c++) oacc[mt][nt][c] = 0.0f;

    for (int kt = 0; kt < 32; kt++) {
        __syncthreads();   // prior PV done reading Vs
        const float* kg = kb + kt * 4096;
        const float* vg = vb + kt * 4096;
#pragma unroll
        for (int i = 0; i < 8; i++) {
            int id = tid + i * 128;
            int m = id >> 4, dc = (id & 15) * 4;
            float4 kv = *(const float4*)(kg + m * 64 + dc);
            float4 vv = *(const float4*)(vg + m * 64 + dc);
            *(float4*)&Ks[m * 68 + dc] =
                make_float4(f2tf_f(kv.x), f2tf_f(kv.y), f2tf_f(kv.z), f2tf_f(kv.w));
            *(float4*)&Vs[m * 68 + dc] =
                make_float4(f2tf_f(vv.x), f2tf_f(vv.y), f2tf_f(vv.z), f2tf_f(vv.w));
        }
        __syncthreads();

        // ---- S = Q K^T (in registers) ----
        float sacc[2][8][4];
#pragma unroll
        for (int mt = 0; mt < 2; mt++)
#pragma unroll
            for (int nt = 0; nt < 8; nt++)
#pragma unroll
                for (int c = 0; c < 4; c++) sacc[mt][nt][c] = 0.0f;

#pragma unroll
        for (int k8 = 0; k8 < 64; k8 += 8) {
            uint32_t af[2][4];
#pragma unroll
            for (int mt = 0; mt < 2; mt++) {
                const int r0 = wm + mt * 16 + gq;
                af[mt][0] = __float_as_uint(Qs[r0 * 68 + k8 + gr]);
                af[mt][1] = __float_as_uint(Qs[(r0 + 8) * 68 + k8 + gr]);
                af[mt][2] = __float_as_uint(Qs[r0 * 68 + k8 + 4 + gr]);
                af[mt][3] = __float_as_uint(Qs[(r0 + 8) * 68 + k8 + 4 + gr]);
            }
#pragma unroll
            for (int nt = 0; nt < 8; nt++) {
                const int n0 = nt * 8 + gq;
                uint32_t bf[2];
                bf[0] = __float_as_uint(Ks[n0 * 68 + k8 + gr]);
                bf[1] = __float_as_uint(Ks[n0 * 68 + k8 + 4 + gr]);
                mma8(sacc[0][nt], af[0], bf);
                mma8(sacc[1][nt], af[1], bf);
            }
        }

        // ---- warp-local online softmax ----
#pragma unroll
        for (int mt = 0; mt < 2; mt++) {
            float tml = -1e30f, tmh = -1e30f;
#pragma unroll
            for (int nt = 0; nt < 8; nt++) {
                const float2 mv = *(const float2*)&msk[kt * 64 + nt * 8 + 2 * gr];
                sacc[mt][nt][0] = sacc[mt][nt][0] * 0.125f + mv.x;
                sacc[mt][nt][1] = sacc[mt][nt][1] * 0.125f + mv.y;
                sacc[mt][nt][2] = sacc[mt][nt][2] * 0.125f + mv.x;
                sacc[mt][nt][3] = sacc[mt][nt][3] * 0.125f + mv.y;
                tml = fmaxf(tml, fmaxf(sacc[mt][nt][0], sacc[mt][nt][1]));
                tmh = fmaxf(tmh, fmaxf(sacc[mt][nt][2], sacc[mt][nt][3]));
            }
            tml = fmaxf(tml, __shfl_xor_sync(0xffffffffu, tml, 1));
            tml = fmaxf(tml, __shfl_xor_sync(0xffffffffu, tml, 2));
            tmh = fmaxf(tmh, __shfl_xor_sync(0xffffffffu, tmh, 1));
            tmh = fmaxf(tmh, __shfl_xor_sync(0xffffffffu, tmh, 2));

            const float nml = fmaxf(rmax[mt][0], tml);
            const float nmh = fmaxf(rmax[mt][1], tmh);
            const float crl = __expf(rmax[mt][0] - nml);
            const float crh = __expf(rmax[mt][1] - nmh);
            rmax[mt][0] = nml;
            rmax[mt][1] = nmh;

            const int r_lo = wm + mt * 16 + gq;
            const int r_hi = r_lo + 8;
            float psl = 0.0f, psh = 0.0f;
#pragma unroll
            for (int nt = 0; nt < 8; nt++) {
                const float p0 = __expf(sacc[mt][nt][0] - nml);
                const float p1 = __expf(sacc[mt][nt][1] - nml);
                const float p2 = __expf(sacc[mt][nt][2] - nmh);
                const float p3 = __expf(sacc[mt][nt][3] - nmh);
                psl += p0 + p1;
                psh += p2 + p3;
                *(float2*)&Ps[r_lo * 68 + nt * 8 + 2 * gr] =
                    make_float2(f2tf_f(p0), f2tf_f(p1));
                *(float2*)&Ps[r_hi * 68 + nt * 8 + 2 * gr] =
                    make_float2(f2tf_f(p2), f2tf_f(p3));
            }
            psl += __shfl_xor_sync(0xffffffffu, psl, 1);
            psl += __shfl_xor_sync(0xffffffffu, psl, 2);
            psh += __shfl_xor_sync(0xffffffffu, psh, 1);
            psh += __shfl_xor_sync(0xffffffffu, psh, 2);
            rsum[mt][0] = rsum[mt][0] * crl + psl;
            rsum[mt][1] = rsum[mt][1] * crh + psh;

#pragma unroll
            for (int nt = 0; nt < 8; nt++) {
                oacc[mt][nt][0] *= crl;
                oacc[mt][nt][1] *= crl;
                oacc[mt][nt][2] *= crh;
                oacc[mt][nt][3] *= crh;
            }
        }
        __syncwarp();   // P visible across lanes of this warp

        // ---- O += P * V ----
#pragma unroll
        for (int k8 = 0; k8 < 64; k8 += 8) {
            uint32_t af[2][4];
#pragma unroll
            for (int mt = 0; mt < 2; mt++) {
                const int r0 = wm + mt * 16 + gq;
                af[mt][0] = __float_as_uint(Ps[r0 * 68 + k8 + gr]);
                af[mt][1] = __float_as_uint(Ps[(r0 + 8) * 68 + k8 + gr]);
                af[mt][2] = __float_as_uint(Ps[r0 * 68 + k8 + 4 + gr]);
                af[mt][3] = __float_as_uint(Ps[(r0 + 8) * 68 + k8 + 4 + gr]);
            }
#pragma unroll
            for (int nt = 0; nt < 8; nt++) {
                const int n0 = nt * 8 + gq;
                uint32_t bf[2];
                bf[0] = __float_as_uint(Vs[(k8 + gr) * 68 + n0]);
                bf[1] = __float_as_uint(Vs[(k8 + 4 + gr) * 68 + n0]);
                mma8(oacc[0][nt], af[0], bf);
                mma8(oacc[1][nt], af[1], bf);
            }
        }
    }

    // epilogue: divide by row sums, write out[b][s][h*64+d]
#pragma unroll
    for (int mt = 0; mt < 2; mt++) {
        const float invl = 1.0f / rsum[mt][0];
        const float invh = 1.0f / rsum[mt][1];
        const int s_lo = qt * QT + wm + mt * 16 + gq;
        const int s_hi = s_lo + 8;
#pragma unroll
        for (int nt = 0; nt < 8; nt++) {
            const int col = h * 64 + nt * 8 + 2 * gr;
            const size_t i0 = ((size_t)(b * SEQ + s_lo)) * 1024 + col;
            const size_t i1 = ((size_t)(b * SEQ + s_hi)) * 1024 + col;
            *(float2*)&out[i0] = make_float2(oacc[mt][nt][0] * invl,
                                             oacc[mt][nt][1] * invl);
            *(float2*)&out[i1] = make_float2(oacc[mt][nt][2] * invh,
                                             oacc[mt][nt][3] * invh);
        }
    }
}

extern "C" void kernel_launch(void* const* d_in, const int* in_sizes, int n_in,
                              void* d_out, int out_size)
{
    const float* hs   = (const float*)d_in[0];
    const float* mask = (const float*)d_in[1];
    const float* rel  = (const float*)d_in[2];
    const float* Wq   = (const float*)d_in[3];
    const float* bq   = (const float*)d_in[4];
    const float* Wk   = (const float*)d_in[5];
    const float* bk   = (const float*)d_in[6];
    const float* Wv   = (const float*)d_in[7];
    const float* bv   = (const float*)d_in[8];
    float* out = (float*)d_out;
    (void)in_sizes; (void)n_in; (void)out_size;

    cudaFuncSetAttribute(attn_mma_kernel, cudaFuncAttributeMaxDynamicSharedMemorySize,
                         ASMEM_FLOATS * (int)sizeof(float));

    dim3 ggrid(HD / 64, (BATCH * SEQ) / 128, 3);
    qkv_mma_kernel<<<ggrid, 256>>>(hs, Wq, bq, Wk, bk, Wv, bv, rel);

    dim3 agrid(SEQ / QT, NHEADS, BATCH);
    attn_mma_kernel<<<agrid, 128, ASMEM_FLOATS * (int)sizeof(float)>>>(mask, out);
}